// round 4
// baseline (speedup 1.0000x reference)
#include <cuda_runtime.h>

#define N_NODES 100000
#define N_EDGES 1600000
#define D 64
#define BN_EPS 1e-5f

#define SCAN_B 1024
#define NBLK ((N_NODES + SCAN_B - 1) / SCAN_B)   // 98

// ---------------- device scratch (no allocations allowed) ----------------
__device__ float g_support[N_NODES * D];   // x @ W
__device__ float g_agg[N_NODES * D];       // aggregated messages
__device__ int   g_deg[N_NODES];           // in-degree histogram
__device__ int   g_rowptr[N_NODES + 1];    // CSR row pointers (by dst)
__device__ int   g_cursor[N_NODES];        // scatter write cursors
__device__ int   g_blockSums[128];
__device__ int   g_blockOffs[128];
__device__ int   g_perm_src[N_EDGES];      // src permuted to dst-grouped order
__device__ float g_perm_w[N_EDGES];        // weight permuted likewise
__device__ float g_colsum[D];
__device__ float g_colsq[D];
__device__ float g_scale[D];
__device__ float g_shift[D];

// ---------------- 0: zero histogram + stats accumulators ----------------
__global__ void zero_kernel() {
    int i = blockIdx.x * blockDim.x + threadIdx.x;
    if (i < N_NODES) g_deg[i] = 0;
    if (i < D) { g_colsum[i] = 0.f; g_colsq[i] = 0.f; }
}

// ---------------- 1: support = x @ W  (fp32 SIMT, W in smem) -------------
// block = 256 threads = 16 rows x 16 col-groups (float4 per thread)
__global__ void gemm_kernel(const float* __restrict__ x,
                            const float* __restrict__ W) {
    __shared__ float4 Ws4[64 * 16];     // W[k][c] as float4 over c
    __shared__ float  xs[16][65];       // padded to kill bank conflicts

    int tid = threadIdx.x;
    const float4* W4 = (const float4*)W;
    #pragma unroll
    for (int i = tid; i < 1024; i += 256) Ws4[i] = W4[i];

    int row0 = blockIdx.x * 16;
    {   // 16 rows x 64 floats = 256 float4, one per thread
        const float4* x4 = (const float4*)(x + (size_t)row0 * D);
        float4 v = x4[tid];
        int r = tid >> 4, k4 = tid & 15;
        xs[r][k4 * 4 + 0] = v.x; xs[r][k4 * 4 + 1] = v.y;
        xs[r][k4 * 4 + 2] = v.z; xs[r][k4 * 4 + 3] = v.w;
    }
    __syncthreads();

    int r = tid >> 4, c4 = tid & 15;
    float4 acc = {0.f, 0.f, 0.f, 0.f};
    #pragma unroll
    for (int k = 0; k < 64; k++) {
        float xv = xs[r][k];
        float4 w = Ws4[k * 16 + c4];
        acc.x += xv * w.x; acc.y += xv * w.y;
        acc.z += xv * w.z; acc.w += xv * w.w;
    }
    ((float4*)g_support)[(size_t)(row0 + r) * 16 + c4] = acc;
}

// ---------------- 2: histogram of edge destinations ----------------------
__global__ void hist_kernel(const int* __restrict__ edge_dst) {
    int e = blockIdx.x * blockDim.x + threadIdx.x;
    if (e < N_EDGES) atomicAdd(&g_deg[__ldg(&edge_dst[e])], 1);
}

// ---------------- 3a: per-block exclusive scan of degrees ----------------
__global__ void scan_block_kernel() {
    __shared__ int sh[SCAN_B];
    int t = threadIdx.x;
    int i = blockIdx.x * SCAN_B + t;
    int v = (i < N_NODES) ? g_deg[i] : 0;
    sh[t] = v;
    __syncthreads();
    for (int off = 1; off < SCAN_B; off <<= 1) {
        int add = (t >= off) ? sh[t - off] : 0;
        __syncthreads();
        sh[t] += add;
        __syncthreads();
    }
    if (i < N_NODES) g_rowptr[i] = sh[t] - v;           // exclusive in-block
    if (t == SCAN_B - 1) g_blockSums[blockIdx.x] = sh[t];
}

// ---------------- 3b: scan the block sums (1 block) -----------------------
__global__ void scan_sums_kernel() {
    __shared__ int sh[128];
    int t = threadIdx.x;
    int v = (t < NBLK) ? g_blockSums[t] : 0;
    sh[t] = v;
    __syncthreads();
    for (int off = 1; off < 128; off <<= 1) {
        int add = (t >= off) ? sh[t - off] : 0;
        __syncthreads();
        sh[t] += add;
        __syncthreads();
    }
    g_blockOffs[t] = sh[t] - v;
}

// ---------------- 3c: add block offsets, init cursors ---------------------
__global__ void add_offsets_kernel() {
    int i = blockIdx.x * SCAN_B + threadIdx.x;
    if (i < N_NODES) {
        int r = g_rowptr[i] + g_blockOffs[blockIdx.x];
        g_rowptr[i] = r;
        g_cursor[i] = r;
    }
    if (i == 0) g_rowptr[N_NODES] = N_EDGES;
}

// ---------------- 4: scatter edges into dst-grouped order -----------------
__global__ void scatter_kernel(const int* __restrict__ edge_src,
                               const int* __restrict__ edge_dst,
                               const float* __restrict__ edge_weight) {
    int e = blockIdx.x * blockDim.x + threadIdx.x;
    if (e < N_EDGES) {
        int d = __ldg(&edge_dst[e]);
        int s = __ldg(&edge_src[e]);
        float w = __ldg(&edge_weight[e]);
        int pos = atomicAdd(&g_cursor[d], 1);
        g_perm_src[pos] = s;
        g_perm_w[pos]   = w;
    }
}

// ---------------- 5: gather-aggregate (16 threads / node) -----------------
// 2x software pipeline: prefetch next edge's (src, w) while the current
// 16B row-gather is outstanding -> MLP 2 against L2 latency.
__global__ void aggregate_kernel() {
    int gt = blockIdx.x * blockDim.x + threadIdx.x;
    int node = gt >> 4;
    int lane = gt & 15;
    if (node >= N_NODES) return;
    int beg = __ldg(&g_rowptr[node]);
    int end = __ldg(&g_rowptr[node + 1]);
    const float4* sup4 = (const float4*)g_support;
    float4 acc = {0.f, 0.f, 0.f, 0.f};

    int e = beg;
    // pairwise: issue both gathers before consuming either
    for (; e + 1 < end; e += 2) {
        int   s0 = __ldg(&g_perm_src[e]);
        int   s1 = __ldg(&g_perm_src[e + 1]);
        float w0 = __ldg(&g_perm_w[e]);
        float w1 = __ldg(&g_perm_w[e + 1]);
        float4 v0 = sup4[(size_t)s0 * 16 + lane];
        float4 v1 = sup4[(size_t)s1 * 16 + lane];
        acc.x += w0 * v0.x; acc.y += w0 * v0.y;
        acc.z += w0 * v0.z; acc.w += w0 * v0.w;
        acc.x += w1 * v1.x; acc.y += w1 * v1.y;
        acc.z += w1 * v1.z; acc.w += w1 * v1.w;
    }
    if (e < end) {
        int   s = __ldg(&g_perm_src[e]);
        float w = __ldg(&g_perm_w[e]);
        float4 v = sup4[(size_t)s * 16 + lane];
        acc.x += w * v.x; acc.y += w * v.y;
        acc.z += w * v.z; acc.w += w * v.w;
    }
    ((float4*)g_agg)[(size_t)node * 16 + lane] = acc;
}

// ---------------- 6: batchnorm column statistics ---------------------------
__global__ void bnstats_kernel() {
    int c = threadIdx.x & 63;
    int rsub = threadIdx.x >> 6;                     // 0..3
    float s = 0.f, sq = 0.f;
    for (int row = blockIdx.x * 4 + rsub; row < N_NODES; row += gridDim.x * 4) {
        float v = g_agg[(size_t)row * D + c];
        s += v; sq += v * v;
    }
    __shared__ float sh1[256], sh2[256];
    sh1[threadIdx.x] = s; sh2[threadIdx.x] = sq;
    __syncthreads();
    if (threadIdx.x < 64) {
        s  = sh1[c] + sh1[c + 64] + sh1[c + 128] + sh1[c + 192];
        sq = sh2[c] + sh2[c + 64] + sh2[c + 128] + sh2[c + 192];
        atomicAdd(&g_colsum[c], s);
        atomicAdd(&g_colsq[c], sq);
    }
}

// ---------------- 7: finalize BN scale/shift (bias cancels with mean) ------
__global__ void finalize_kernel(const float* __restrict__ gamma,
                                const float* __restrict__ beta) {
    int c = threadIdx.x;
    float mean = g_colsum[c] * (1.f / N_NODES);
    float var  = g_colsq[c] * (1.f / N_NODES) - mean * mean;
    float inv  = rsqrtf(var + BN_EPS);
    float sc   = gamma[c] * inv;
    g_scale[c] = sc;
    g_shift[c] = beta[c] - mean * sc;
}

// ---------------- 8: normalize + ReLU to output ----------------------------
__global__ void out_kernel(float* __restrict__ out) {
    int i = blockIdx.x * blockDim.x + threadIdx.x;
    if (i < N_NODES * 16) {
        int c4 = i & 15;
        float4 a  = ((const float4*)g_agg)[i];
        float4 sc = ((const float4*)g_scale)[c4];
        float4 sf = ((const float4*)g_shift)[c4];
        float4 o;
        o.x = fmaxf(fmaf(a.x, sc.x, sf.x), 0.f);
        o.y = fmaxf(fmaf(a.y, sc.y, sf.y), 0.f);
        o.z = fmaxf(fmaf(a.z, sc.z, sf.z), 0.f);
        o.w = fmaxf(fmaf(a.w, sc.w, sf.w), 0.f);
        ((float4*)out)[i] = o;
    }
}

// ---------------- launcher -------------------------------------------------
extern "C" void kernel_launch(void* const* d_in, const int* in_sizes, int n_in,
                              void* d_out, int out_size) {
    const float* x           = (const float*)d_in[0];
    const int*   edge_src    = (const int*)d_in[1];
    const int*   edge_dst    = (const int*)d_in[2];
    const float* edge_weight = (const float*)d_in[3];
    const float* W           = (const float*)d_in[4];
    // d_in[5] = bias: mathematically cancels inside BatchNorm — unused.
    const float* gamma       = (const float*)d_in[6];
    const float* beta        = (const float*)d_in[7];
    float*       out         = (float*)d_out;

    zero_kernel<<<(N_NODES + 255) / 256, 256>>>();
    gemm_kernel<<<N_NODES / 16, 256>>>(x, W);
    hist_kernel<<<(N_EDGES + 511) / 512, 512>>>(edge_dst);
    scan_block_kernel<<<NBLK, SCAN_B>>>();
    scan_sums_kernel<<<1, 128>>>();
    add_offsets_kernel<<<NBLK, SCAN_B>>>();
    scatter_kernel<<<(N_EDGES + 511) / 512, 512>>>(edge_src, edge_dst, edge_weight);
    aggregate_kernel<<<(N_NODES * 16) / 256, 256>>>();
    bnstats_kernel<<<256, 256>>>();
    finalize_kernel<<<1, 64>>>(gamma, beta);
    out_kernel<<<(N_NODES * 16) / 256, 256>>>(out);
}